// round 11
// baseline (speedup 1.0000x reference)
#include <cuda_runtime.h>
#include <cuda_bf16.h>

#define NPTS   65536
#define CHN    256
#define BATCH  16
#define LOUT   8192
#define LOG2L  13

// g_off[b] = first index with batch id >= b; g_off[BATCH] = NPTS.
__device__ int g_off[BATCH + 1];

// ------------------------------------------------------- boundary search ---
// Single block, 16 warps. Warp k (k>=1) lower_bounds key k over the sorted
// batch array via 32-ary cooperative search (3 ballot rounds + final probe).
// Warp 0 writes the trivial ends. ~0.7us vs 4.8us for the scan kernel.
// Fires the PDL trigger at entry so the gather grid launches concurrently.
__global__ void boundary_kernel(const int* __restrict__ batch) {
    asm volatile("griddepcontrol.launch_dependents;");
    int w = threadIdx.x >> 5, L = threadIdx.x & 31;
    if (w == 0) {
        if (L == 0) { g_off[0] = 0; g_off[BATCH] = NPTS; }
        return;
    }
    int key = w;                          // 1..15
    int lo = -1;
    int s = 2048;                         // 65536 -> 2048 -> 64 -> 2
    #pragma unroll
    for (int lev = 0; lev < 3; lev++) {
        int pos = lo + (L + 1) * s;
        int val = (pos < NPTS) ? __ldg(&batch[pos]) : 0x7fffffff;
        unsigned m = __ballot_sync(0xffffffffu, val < key);
        lo += __popc(m) * s;
        s >>= 5;
    }
    bool pred = false;
    if (L < 2) {
        int pos = lo + 1 + L;
        pred = (pos < NPTS) && (__ldg(&batch[pos]) < key);
    }
    unsigned m = __ballot_sync(0xffffffffu, pred);
    if (L == 0) g_off[key] = lo + 1 + __popc(m);
}

// ----------------------------------------------------------- main gather ---
// R8 body (best measured). griddepcontrol.wait before reading g_off.
#define PT_BLOCKS 128

__global__ __launch_bounds__(256)
void gather_kernel(const float* __restrict__ px,
                   const float4* __restrict__ feat4,
                   float* __restrict__ out_point,
                   float* __restrict__ out_feat) {
    __shared__ int s_off, s_cnt;
    int bid = blockIdx.x;
    int tid = threadIdx.x;

    if (bid < PT_BLOCKS) {
        int idx = bid * 256 + tid;            // 0..32767
        int b = idx >> 11;
        int j = (idx & 2047) * 4;
        asm volatile("griddepcontrol.wait;");
        if (tid == 0) { s_off = g_off[b]; s_cnt = g_off[b + 1] - g_off[b]; }
        __syncthreads();
        int off = s_off, cnt = s_cnt;
        float4 ox, oy, oz;
        #pragma unroll
        for (int t = 0; t < 4; t++) {
            int src = off + (int)(((unsigned)((j + t) * cnt)) >> LOG2L);
            const float* p = px + 3 * src;
            ((float*)&ox)[t] = p[0];
            ((float*)&oy)[t] = p[1];
            ((float*)&oz)[t] = p[2];
        }
        size_t base = (size_t)b * 3 * LOUT + j;
        __stcs((float4*)(out_point + base),            ox);
        __stcs((float4*)(out_point + base + LOUT),     oy);
        __stcs((float4*)(out_point + base + 2 * LOUT), oz);
        return;
    }

    // ---- features ----
    int idx = (bid - PT_BLOCKS) * 256 + tid;  // 0 .. 2097151
    int jq = idx & 2047;
    int c4 = (idx >> 11) & 63;
    int b  = idx >> 17;                       // block-uniform
    int j0 = jq * 4;
    asm volatile("griddepcontrol.wait;");
    if (tid == 0) { s_off = g_off[b]; s_cnt = g_off[b + 1] - g_off[b]; }
    __syncthreads();
    int off = s_off, cnt = s_cnt;

    // Monotone source rows; load endpoints, select/rare-load interiors.
    int r0 = off + (int)(((unsigned)((j0 + 0) * cnt)) >> LOG2L);
    int r1 = off + (int)(((unsigned)((j0 + 1) * cnt)) >> LOG2L);
    int r2 = off + (int)(((unsigned)((j0 + 2) * cnt)) >> LOG2L);
    int r3 = off + (int)(((unsigned)((j0 + 3) * cnt)) >> LOG2L);

    const float4* fb = feat4 + c4;
    float4 A = __ldg(fb + (size_t)r0 * (CHN / 4));
    float4 D = __ldg(fb + (size_t)r3 * (CHN / 4));
    float4 v1 = (r1 == r0) ? A : D;
    if (r1 > r0 && r1 < r3) v1 = __ldg(fb + (size_t)r1 * (CHN / 4));
    float4 v2 = (r2 == r3) ? D : A;
    if (r2 > r0 && r2 < r3) v2 = __ldg(fb + (size_t)r2 * (CHN / 4));

    float* ob = out_feat + ((size_t)b * CHN + 4 * c4) * LOUT + j0;
    float4 o;
    o.x = A.x;  o.y = v1.x; o.z = v2.x; o.w = D.x;
    __stcs((float4*)(ob + 0 * LOUT), o);
    o.x = A.y;  o.y = v1.y; o.z = v2.y; o.w = D.y;
    __stcs((float4*)(ob + 1 * LOUT), o);
    o.x = A.z;  o.y = v1.z; o.z = v2.z; o.w = D.z;
    __stcs((float4*)(ob + 2 * LOUT), o);
    o.x = A.w;  o.y = v1.w; o.z = v2.w; o.w = D.w;
    __stcs((float4*)(ob + 3 * LOUT), o);
}

// ------------------------------------------------------------- launch ------
extern "C" void kernel_launch(void* const* d_in, const int* in_sizes, int n_in,
                              void* d_out, int out_size) {
    const float* points_x = (const float*)d_in[0];   // [N,3]
    const float* feat     = (const float*)d_in[1];   // [N,C]
    const int*   batch    = (const int*)d_in[2];     // [N]

    float* out_point = (float*)d_out;                              // [B,3,L]
    float* out_feat  = (float*)d_out + (size_t)BATCH * 3 * LOUT;   // [B,C,L]

    boundary_kernel<<<1, 512>>>(batch);

    // Gather launched as a programmatic dependent of boundary_kernel.
    cudaLaunchConfig_t cfg = {};
    cfg.gridDim  = dim3(PT_BLOCKS + 8192, 1, 1);
    cfg.blockDim = dim3(256, 1, 1);
    cfg.dynamicSmemBytes = 0;
    cfg.stream = 0;
    cudaLaunchAttribute attr[1];
    attr[0].id = cudaLaunchAttributeProgrammaticStreamSerialization;
    attr[0].val.programmaticStreamSerializationAllowed = 1;
    cfg.attrs = attr;
    cfg.numAttrs = 1;
    cudaLaunchKernelEx(&cfg, gather_kernel,
                       points_x, (const float4*)feat, out_point, out_feat);
}

// round 12
// speedup vs baseline: 1.0372x; 1.0372x over previous
#include <cuda_runtime.h>
#include <cuda_bf16.h>

#define NPTS   65536
#define CHN    256
#define BATCH  16
#define LOUT   8192
#define LOG2L  13

// g_off[b] = first index with batch id >= b; g_off[BATCH] = NPTS.
__device__ int g_off[BATCH + 1];

// ------------------------------------------------------- boundary detect ---
// batch sorted; int4 loads, boundary write-out, no atomics. PDL trigger at
// entry so the gather grid launches while this runs.
__global__ void boundary_kernel(const int* __restrict__ batch) {
    asm volatile("griddepcontrol.launch_dependents;");
    int t = blockIdx.x * blockDim.x + threadIdx.x;   // 0 .. NPTS/4-1
    if (t >= NPTS / 4) return;
    int4 v = ((const int4*)batch)[t];
    int prev = (t == 0) ? -1 : __ldg(&batch[4 * t - 1]);
    for (int bb = prev + 1; bb <= v.x; bb++) g_off[bb] = 4 * t + 0;
    for (int bb = v.x + 1;  bb <= v.y; bb++) g_off[bb] = 4 * t + 1;
    for (int bb = v.y + 1;  bb <= v.z; bb++) g_off[bb] = 4 * t + 2;
    for (int bb = v.z + 1;  bb <= v.w; bb++) g_off[bb] = 4 * t + 3;
    if (t == NPTS / 4 - 1)
        for (int bb = v.w + 1; bb <= BATCH; bb++) g_off[bb] = NPTS;
}

// ----------------------------------------------------------- main gather ---
// blocks [0, PT_BLOCKS): points. blocks [PT_BLOCKS, PT_BLOCKS+4096): features.
// Feature thread owns TWO j-quads, 128 j apart (lane = consecutive jq within
// each quad -> both store groups are 512B-contiguous STG.128). Doubles load
// MLP (~4.4 LDG.128 in flight) to cover L2/DRAM latency; halves per-block
// fixed costs. Endpoint-dedup loads per quad (R8 body).
#define PT_BLOCKS 128

__device__ __forceinline__ void do_quad(const float4* __restrict__ fb,
                                        float* __restrict__ obase,
                                        int off, int cnt, int j0) {
    int r0 = off + (int)(((unsigned)((j0 + 0) * cnt)) >> LOG2L);
    int r1 = off + (int)(((unsigned)((j0 + 1) * cnt)) >> LOG2L);
    int r2 = off + (int)(((unsigned)((j0 + 2) * cnt)) >> LOG2L);
    int r3 = off + (int)(((unsigned)((j0 + 3) * cnt)) >> LOG2L);

    float4 A = __ldg(fb + (size_t)r0 * (CHN / 4));
    float4 D = __ldg(fb + (size_t)r3 * (CHN / 4));
    float4 v1 = (r1 == r0) ? A : D;
    if (r1 > r0 && r1 < r3) v1 = __ldg(fb + (size_t)r1 * (CHN / 4));
    float4 v2 = (r2 == r3) ? D : A;
    if (r2 > r0 && r2 < r3) v2 = __ldg(fb + (size_t)r2 * (CHN / 4));

    float* ob = obase + j0;
    float4 o;
    o.x = A.x;  o.y = v1.x; o.z = v2.x; o.w = D.x;
    __stcs((float4*)(ob + 0 * LOUT), o);
    o.x = A.y;  o.y = v1.y; o.z = v2.y; o.w = D.y;
    __stcs((float4*)(ob + 1 * LOUT), o);
    o.x = A.z;  o.y = v1.z; o.z = v2.z; o.w = D.z;
    __stcs((float4*)(ob + 2 * LOUT), o);
    o.x = A.w;  o.y = v1.w; o.z = v2.w; o.w = D.w;
    __stcs((float4*)(ob + 3 * LOUT), o);
}

__global__ __launch_bounds__(256)
void gather_kernel(const float* __restrict__ px,
                   const float4* __restrict__ feat4,
                   float* __restrict__ out_point,
                   float* __restrict__ out_feat) {
    __shared__ int s_off, s_cnt;
    int bid = blockIdx.x;
    int tid = threadIdx.x;

    if (bid < PT_BLOCKS) {
        int idx = bid * 256 + tid;            // 0..32767
        int b = idx >> 11;
        int j = (idx & 2047) * 4;
        asm volatile("griddepcontrol.wait;");
        if (tid == 0) { s_off = g_off[b]; s_cnt = g_off[b + 1] - g_off[b]; }
        __syncthreads();
        int off = s_off, cnt = s_cnt;
        float4 ox, oy, oz;
        #pragma unroll
        for (int t = 0; t < 4; t++) {
            int src = off + (int)(((unsigned)((j + t) * cnt)) >> LOG2L);
            const float* p = px + 3 * src;
            ((float*)&ox)[t] = p[0];
            ((float*)&oy)[t] = p[1];
            ((float*)&oz)[t] = p[2];
        }
        size_t base = (size_t)b * 3 * LOUT + j;
        __stcs((float4*)(out_point + base),            ox);
        __stcs((float4*)(out_point + base + LOUT),     oy);
        __stcs((float4*)(out_point + base + 2 * LOUT), oz);
        return;
    }

    // ---- features: block = (b, seg, c4); 4 segs of 512 jq; warp w covers
    // jq window [seg*512 + w*64, +64): quads at +L and +L+32.
    int idx  = bid - PT_BLOCKS;               // 0..4095
    int c4   = idx & 63;
    int seg  = (idx >> 6) & 3;
    int b    = idx >> 8;                      // block-uniform
    int w    = tid >> 5, L = tid & 31;
    asm volatile("griddepcontrol.wait;");
    if (tid == 0) { s_off = g_off[b]; s_cnt = g_off[b + 1] - g_off[b]; }
    __syncthreads();
    int off = s_off, cnt = s_cnt;

    int jq0 = seg * 512 + w * 64 + L;
    const float4* fb = feat4 + c4;
    float* obase = out_feat + ((size_t)b * CHN + 4 * c4) * LOUT;

    do_quad(fb, obase, off, cnt, jq0 * 4);
    do_quad(fb, obase, off, cnt, (jq0 + 32) * 4);
}

// ------------------------------------------------------------- launch ------
extern "C" void kernel_launch(void* const* d_in, const int* in_sizes, int n_in,
                              void* d_out, int out_size) {
    const float* points_x = (const float*)d_in[0];   // [N,3]
    const float* feat     = (const float*)d_in[1];   // [N,C]
    const int*   batch    = (const int*)d_in[2];     // [N]

    float* out_point = (float*)d_out;                              // [B,3,L]
    float* out_feat  = (float*)d_out + (size_t)BATCH * 3 * LOUT;   // [B,C,L]

    boundary_kernel<<<64, 256>>>(batch);

    // Gather launched as a programmatic dependent of boundary_kernel.
    cudaLaunchConfig_t cfg = {};
    cfg.gridDim  = dim3(PT_BLOCKS + 4096, 1, 1);
    cfg.blockDim = dim3(256, 1, 1);
    cfg.dynamicSmemBytes = 0;
    cfg.stream = 0;
    cudaLaunchAttribute attr[1];
    attr[0].id = cudaLaunchAttributeProgrammaticStreamSerialization;
    attr[0].val.programmaticStreamSerializationAllowed = 1;
    cfg.attrs = attr;
    cfg.numAttrs = 1;
    cudaLaunchKernelEx(&cfg, gather_kernel,
                       points_x, (const float4*)feat, out_point, out_feat);
}